// round 3
// baseline (speedup 1.0000x reference)
#include <cuda_runtime.h>
#include <cuda_bf16.h>
#include <math.h>

#define B_ 4
#define L_ 2048
#define H_ 512
#define N_ 8
#define D_ 64

// ---------------- scratch (static device globals; no allocation) ----------------
__device__ float g_Wqkv[H_ * 3 * H_];   // [h][mat*512 + n*64 + d]
__device__ float g_bqkv[3 * H_];
__device__ float g_Wrp[H_ * H_];        // [h][n*64+d]
__device__ float g_brp[H_];
__device__ float g_WcT[H_ * H_];        // [k][c] = Wc[c][k]
__device__ float g_W1T[H_ * H_];
__device__ float g_W2T[H_ * H_];
__device__ float g_q[B_ * N_ * L_ * D_];
__device__ float g_k[B_ * N_ * L_ * D_];
__device__ float g_v[B_ * N_ * L_ * D_];
__device__ float g_rb[N_ * L_ * D_];
__device__ float g_attn[B_ * L_ * H_];
__device__ float g_y1[B_ * L_ * H_];
__device__ float g_a[B_ * L_ * H_];
__device__ float g_h1[B_ * L_ * H_];
__device__ float g_y2[B_ * L_ * H_];

// ---------------- pack kernel ----------------
__global__ void pack_kernel(const float* __restrict__ Wq, const float* __restrict__ bq,
                            const float* __restrict__ Wk, const float* __restrict__ bk,
                            const float* __restrict__ Wv, const float* __restrict__ bv,
                            const float* __restrict__ Wr, const float* __restrict__ br,
                            const float* __restrict__ Wc, const float* __restrict__ W1,
                            const float* __restrict__ W2) {
    int idx = blockIdx.x * blockDim.x + threadIdx.x;
    int stride = gridDim.x * blockDim.x;
    // Wqkv: B matrix [h=512][c=1536], c = mat*512 + n*64 + d ; W{q,k,v}[n][h][d]
    for (int i = idx; i < 512 * 1536; i += stride) {
        int h = i / 1536, c = i % 1536;
        int mat = c >> 9, rem = c & 511, n = rem >> 6, d = rem & 63;
        const float* W = (mat == 0) ? Wq : ((mat == 1) ? Wk : Wv);
        g_Wqkv[i] = W[(n * 512 + h) * 64 + d];
    }
    for (int i = idx; i < 1536; i += stride) {
        int mat = i >> 9, rem = i & 511;
        const float* bb = (mat == 0) ? bq : ((mat == 1) ? bk : bv);
        g_bqkv[i] = bb[rem];
    }
    for (int i = idx; i < 512 * 512; i += stride) {
        int h = i >> 9, c = i & 511;
        int n = c >> 6, d = c & 63;
        g_Wrp[i] = Wr[(n * 512 + h) * 64 + d];
    }
    for (int i = idx; i < 512; i += stride) g_brp[i] = br[i];
    for (int i = idx; i < 512 * 512; i += stride) {
        int k = i >> 9, c = i & 511;
        g_WcT[i] = Wc[c * 512 + k];
        g_W1T[i] = W1[c * 512 + k];
        g_W2T[i] = W2[c * 512 + k];
    }
}

__device__ __forceinline__ float gelu_f(float v) {
    return 0.5f * v * (1.0f + erff(v * 0.70710678118654752f));
}

// ---------------- generic 64x64-tile SGEMM, K=512 ----------------
// MODE 0: qkv scatter (+bqkv)   MODE 1: r scatter (+brp)
// MODE 2: C = acc + bias + res  MODE 3: C = gelu(acc + bias)
template <int MODE>
__global__ void gemm64(const float* __restrict__ A, const float* __restrict__ Bm,
                       const float* __restrict__ bias, const float* __restrict__ res,
                       float* __restrict__ C, int Nc,
                       float* __restrict__ qd, float* __restrict__ kd, float* __restrict__ vd) {
    const int K = 512;
    __shared__ float As[16][68];
    __shared__ float Bs[16][68];
    int tid = threadIdx.x;
    int tx = tid & 15, ty = tid >> 4;
    int m0 = blockIdx.y * 64, c0 = blockIdx.x * 64;
    float acc[4][4];
#pragma unroll
    for (int r = 0; r < 4; r++)
#pragma unroll
        for (int c = 0; c < 4; c++) acc[r][c] = 0.f;

    int am = tid >> 2, ak = (tid & 3) * 4;
    int bk = tid >> 4, bcol = (tid & 15) * 4;

    for (int k0 = 0; k0 < K; k0 += 16) {
        float4 av = *(const float4*)&A[(m0 + am) * K + k0 + ak];
        As[ak + 0][am] = av.x;
        As[ak + 1][am] = av.y;
        As[ak + 2][am] = av.z;
        As[ak + 3][am] = av.w;
        *(float4*)&Bs[bk][bcol] = *(const float4*)&Bm[(k0 + bk) * Nc + c0 + bcol];
        __syncthreads();
#pragma unroll
        for (int kk = 0; kk < 16; kk++) {
            float4 a4 = *(const float4*)&As[kk][ty * 4];
            float4 b4 = *(const float4*)&Bs[kk][tx * 4];
            float aa[4] = {a4.x, a4.y, a4.z, a4.w};
            float bb[4] = {b4.x, b4.y, b4.z, b4.w};
#pragma unroll
            for (int r = 0; r < 4; r++)
#pragma unroll
                for (int c = 0; c < 4; c++) acc[r][c] += aa[r] * bb[c];
        }
        __syncthreads();
    }

#pragma unroll
    for (int r = 0; r < 4; r++) {
#pragma unroll
        for (int c = 0; c < 4; c++) {
            int m = m0 + ty * 4 + r;
            int cg = c0 + tx * 4 + c;
            float val = acc[r][c] + bias[cg];
            if (MODE == 0) {
                int mat = cg >> 9, rem = cg & 511, n = rem >> 6, d = rem & 63;
                float* dst = (mat == 0) ? qd : ((mat == 1) ? kd : vd);
                int bI = m >> 11, l = m & 2047;
                dst[((bI * 8 + n) * 2048 + l) * 64 + d] = val;
            } else if (MODE == 1) {
                int n = cg >> 6, d = cg & 63;
                C[(n * 2048 + m) * 64 + d] = val;
            } else if (MODE == 2) {
                C[m * Nc + cg] = val + res[m * Nc + cg];
            } else {
                C[m * Nc + cg] = gelu_f(val);
            }
        }
    }
}

// ---------------- fused causal rel-pos flash attention ----------------
// scores[i,j] = (qc[i]·k[j] + qp[i]·r[L-1-i+j]) / 8, causal j<=i, online softmax.
#define ATTN_SMEM_BYTES ((4 * 64 * 68 + 64 * 132 + 64) * 4)

__global__ void attn_kernel(const float* __restrict__ qg, const float* __restrict__ kg,
                            const float* __restrict__ vg, const float* __restrict__ rg,
                            const float* __restrict__ cb, const float* __restrict__ pb,
                            float* __restrict__ outg) {
    extern __shared__ float sm[];
    float* Qcs = sm;                      // [64][68]  row-major (i, d)
    float* Kst = sm + 4352;               // [64][68]  d-major (d, j)
    float* Vs  = sm + 2 * 4352;           // [64][68]  (j, d)
    float* Ss  = sm + 3 * 4352;           // [64][68]  P tile
    float* Rst = sm + 4 * 4352;           // [64][132] d-major (d, pp)
    float* dlt = sm + 4 * 4352 + 8448;    // [64]  pos_bias - content_bias

    const int tid = threadIdx.x;
    const int tx = tid & 15, ty = tid >> 4;
    const int ib = blockIdx.x, bn = blockIdx.y;
    const int n = bn & 7, b = bn >> 3;
    const int I0 = ib * 64;

    const int lrow = tid >> 4;        // 0..15
    const int ld0 = (tid & 15) * 4;   // 0..60

    const float* qbase = qg + (bn * L_ + I0) * D_;
    float4 cbv = *(const float4*)&cb[n * 64 + ld0];
#pragma unroll
    for (int t = 0; t < 4; t++) {
        int rr = lrow + t * 16;
        float4 qv = *(const float4*)&qbase[rr * 64 + ld0];
        float* dst = &Qcs[rr * 68 + ld0];
        dst[0] = qv.x + cbv.x;
        dst[1] = qv.y + cbv.y;
        dst[2] = qv.z + cbv.z;
        dst[3] = qv.w + cbv.w;
    }
    if (tid < 64) dlt[tid] = pb[n * 64 + tid] - cb[n * 64 + tid];

    float mrow[4], lsum[4], o[4][4];
#pragma unroll
    for (int r = 0; r < 4; r++) {
        mrow[r] = -1e30f;
        lsum[r] = 0.f;
#pragma unroll
        for (int c = 0; c < 4; c++) o[r][c] = 0.f;
    }

    const int r0 = ty * 4, c0 = tx * 4;
    const int wbase = 60 - r0 + c0;   // multiple of 4, in [0,120]

    for (int jb = 0; jb <= ib; jb++) {
        __syncthreads();
        const int J0 = jb * 64;
        const int pmin = L_ - 64 - I0 + J0;
        const float* kbase = kg + (bn * L_ + J0) * D_;
        const float* vbase = vg + (bn * L_ + J0) * D_;
#pragma unroll
        for (int t = 0; t < 4; t++) {
            int j = lrow + t * 16;
            float4 kv = *(const float4*)&kbase[j * 64 + ld0];
            Kst[(ld0 + 0) * 68 + j] = kv.x;
            Kst[(ld0 + 1) * 68 + j] = kv.y;
            Kst[(ld0 + 2) * 68 + j] = kv.z;
            Kst[(ld0 + 3) * 68 + j] = kv.w;
            *(float4*)&Vs[j * 68 + ld0] = *(const float4*)&vbase[j * 64 + ld0];
        }
        const float* rbase = rg + n * (L_ * D_);
#pragma unroll
        for (int t = 0; t < 8; t++) {
            int pp = lrow + t * 16;
            int p = pmin + pp;
            float4 rv = make_float4(0.f, 0.f, 0.f, 0.f);
            if (p < L_) rv = *(const float4*)&rbase[p * 64 + ld0];
            Rst[(ld0 + 0) * 132 + pp] = rv.x;
            Rst[(ld0 + 1) * 132 + pp] = rv.y;
            Rst[(ld0 + 2) * 132 + pp] = rv.z;
            Rst[(ld0 + 3) * 132 + pp] = rv.w;
        }
        __syncthreads();

        float s[4][4];
#pragma unroll
        for (int r = 0; r < 4; r++)
#pragma unroll
            for (int c = 0; c < 4; c++) s[r][c] = 0.f;

#pragma unroll 4
        for (int kk = 0; kk < 64; kk++) {
            float d = dlt[kk];
            float aq[4], ap[4];
#pragma unroll
            for (int r = 0; r < 4; r++) {
                aq[r] = Qcs[(r0 + r) * 68 + kk];
                ap[r] = aq[r] + d;
            }
            float4 kb = *(const float4*)&Kst[kk * 68 + c0];
            float kbv[4] = {kb.x, kb.y, kb.z, kb.w};
            float4 w0 = *(const float4*)&Rst[kk * 132 + wbase];
            float4 w1 = *(const float4*)&Rst[kk * 132 + wbase + 4];
            float w[8] = {w0.x, w0.y, w0.z, w0.w, w1.x, w1.y, w1.z, w1.w};
#pragma unroll
            for (int r = 0; r < 4; r++)
#pragma unroll
                for (int c = 0; c < 4; c++)
                    s[r][c] += aq[r] * kbv[c] + ap[r] * w[3 - r + c];
        }

        const bool diag = (jb == ib);
#pragma unroll
        for (int r = 0; r < 4; r++)
#pragma unroll
            for (int c = 0; c < 4; c++) {
                s[r][c] *= 0.125f;
                if (diag && (J0 + c0 + c) > (I0 + r0 + r)) s[r][c] = -1e30f;
            }

#pragma unroll
        for (int r = 0; r < 4; r++) {
            float rm = fmaxf(fmaxf(s[r][0], s[r][1]), fmaxf(s[r][2], s[r][3]));
#pragma unroll
            for (int mk = 8; mk >= 1; mk >>= 1)
                rm = fmaxf(rm, __shfl_xor_sync(0xffffffffu, rm, mk));
            float mn = fmaxf(mrow[r], rm);
            float alpha = __expf(mrow[r] - mn);
            mrow[r] = mn;
            float rs = 0.f;
#pragma unroll
            for (int c = 0; c < 4; c++) {
                s[r][c] = __expf(s[r][c] - mn);
                rs += s[r][c];
            }
#pragma unroll
            for (int mk = 8; mk >= 1; mk >>= 1)
                rs += __shfl_xor_sync(0xffffffffu, rs, mk);
            lsum[r] = lsum[r] * alpha + rs;
#pragma unroll
            for (int c = 0; c < 4; c++) o[r][c] *= alpha;
        }

#pragma unroll
        for (int r = 0; r < 4; r++)
            *(float4*)&Ss[(r0 + r) * 68 + c0] = make_float4(s[r][0], s[r][1], s[r][2], s[r][3]);
        __syncthreads();

#pragma unroll 8
        for (int jj = 0; jj < 64; jj++) {
            float ap2[4];
#pragma unroll
            for (int r = 0; r < 4; r++) ap2[r] = Ss[(r0 + r) * 68 + jj];
            float4 bv = *(const float4*)&Vs[jj * 68 + c0];
            float bvv[4] = {bv.x, bv.y, bv.z, bv.w};
#pragma unroll
            for (int r = 0; r < 4; r++)
#pragma unroll
                for (int c = 0; c < 4; c++) o[r][c] += ap2[r] * bvv[c];
        }
    }

#pragma unroll
    for (int r = 0; r < 4; r++) {
        float inv = 1.0f / lsum[r];
        float* od = &outg[(b * L_ + I0 + r0 + r) * H_ + n * 64 + c0];
        od[0] = o[r][0] * inv;
        od[1] = o[r][1] * inv;
        od[2] = o[r][2] * inv;
        od[3] = o[r][3] * inv;
    }
}

// ---------------- layernorm (eps=1e-12), 1 block per row of 512 ----------------
__global__ void ln_kernel(const float* __restrict__ in, const float* __restrict__ w,
                          const float* __restrict__ bparm, float* __restrict__ out) {
    __shared__ float red[8];
    __shared__ float stat[2];
    int row = blockIdx.x, tid = threadIdx.x;
    const float* xr = in + row * H_;
    float v0 = xr[tid], v1 = xr[tid + 256];
    float s = v0 + v1;
#pragma unroll
    for (int mk = 16; mk >= 1; mk >>= 1) s += __shfl_xor_sync(0xffffffffu, s, mk);
    if ((tid & 31) == 0) red[tid >> 5] = s;
    __syncthreads();
    if (tid == 0) {
        float t = 0;
#pragma unroll
        for (int i = 0; i < 8; i++) t += red[i];
        stat[0] = t * (1.0f / H_);
    }
    __syncthreads();
    float u = stat[0];
    float d0 = v0 - u, d1 = v1 - u;
    float q = d0 * d0 + d1 * d1;
#pragma unroll
    for (int mk = 16; mk >= 1; mk >>= 1) q += __shfl_xor_sync(0xffffffffu, q, mk);
    __syncthreads();
    if ((tid & 31) == 0) red[tid >> 5] = q;
    __syncthreads();
    if (tid == 0) {
        float t = 0;
#pragma unroll
        for (int i = 0; i < 8; i++) t += red[i];
        stat[1] = rsqrtf(t * (1.0f / H_) + 1e-12f);
    }
    __syncthreads();
    float inv = stat[1];
    out[row * H_ + tid] = w[tid] * d0 * inv + bparm[tid];
    out[row * H_ + tid + 256] = w[tid + 256] * d1 * inv + bparm[tid + 256];
}

// ---------------- launch ----------------
extern "C" void kernel_launch(void* const* d_in, const int* in_sizes, int n_in,
                              void* d_out, int out_size) {
    (void)in_sizes; (void)n_in; (void)out_size;
    const float* x  = (const float*)d_in[0];
    const float* pe = (const float*)d_in[1];
    const float* Wq = (const float*)d_in[2];
    const float* bq = (const float*)d_in[3];
    const float* Wk = (const float*)d_in[4];
    const float* bk = (const float*)d_in[5];
    const float* Wv = (const float*)d_in[6];
    const float* bv = (const float*)d_in[7];
    const float* Wr = (const float*)d_in[8];
    const float* br = (const float*)d_in[9];
    const float* cb = (const float*)d_in[10];
    const float* pb = (const float*)d_in[11];
    const float* Wc = (const float*)d_in[12];
    const float* bc = (const float*)d_in[13];
    const float* W1 = (const float*)d_in[14];
    const float* b1 = (const float*)d_in[15];
    const float* W2 = (const float*)d_in[16];
    const float* b2 = (const float*)d_in[17];
    const float* lnw = (const float*)d_in[18];
    const float* lnb = (const float*)d_in[19];
    float* out = (float*)d_out;

    float *pWqkv, *pbqkv, *pWrp, *pbrp, *pWcT, *pW1T, *pW2T;
    float *pq, *pk, *pv, *pr, *pattn, *py1, *pa, *ph1, *py2;
    cudaGetSymbolAddress((void**)&pWqkv, g_Wqkv);
    cudaGetSymbolAddress((void**)&pbqkv, g_bqkv);
    cudaGetSymbolAddress((void**)&pWrp, g_Wrp);
    cudaGetSymbolAddress((void**)&pbrp, g_brp);
    cudaGetSymbolAddress((void**)&pWcT, g_WcT);
    cudaGetSymbolAddress((void**)&pW1T, g_W1T);
    cudaGetSymbolAddress((void**)&pW2T, g_W2T);
    cudaGetSymbolAddress((void**)&pq, g_q);
    cudaGetSymbolAddress((void**)&pk, g_k);
    cudaGetSymbolAddress((void**)&pv, g_v);
    cudaGetSymbolAddress((void**)&pr, g_rb);
    cudaGetSymbolAddress((void**)&pattn, g_attn);
    cudaGetSymbolAddress((void**)&py1, g_y1);
    cudaGetSymbolAddress((void**)&pa, g_a);
    cudaGetSymbolAddress((void**)&ph1, g_h1);
    cudaGetSymbolAddress((void**)&py2, g_y2);

    cudaFuncSetAttribute(attn_kernel, cudaFuncAttributeMaxDynamicSharedMemorySize,
                         ATTN_SMEM_BYTES);

    // 1. pack weights
    pack_kernel<<<768, 256>>>(Wq, bq, Wk, bk, Wv, bv, Wr, br, Wc, W1, W2);

    // 2. QKV projection: (8192x512) @ (512x1536), scatter into per-head layout
    gemm64<0><<<dim3(24, 128), 256>>>(x, pWqkv, pbqkv, nullptr, nullptr, 1536, pq, pk, pv);

    // 3. R projection: (2048x512) @ (512x512)
    gemm64<1><<<dim3(8, 32), 256>>>(pe, pWrp, pbrp, nullptr, pr, 512, nullptr, nullptr, nullptr);

    // 4. fused causal rel-pos attention
    attn_kernel<<<dim3(L_ / 64, B_ * N_), 256, ATTN_SMEM_BYTES>>>(pq, pk, pv, pr, cb, pb, pattn);

    // 5. output projection + residual(x)
    gemm64<2><<<dim3(8, 128), 256>>>(pattn, pWcT, bc, x, py1, 512, nullptr, nullptr, nullptr);

    // 6. layernorm -> a
    ln_kernel<<<B_ * L_, 256>>>(py1, lnw, lnb, pa);

    // 7. FFN up + GELU
    gemm64<3><<<dim3(8, 128), 256>>>(pa, pW1T, b1, nullptr, ph1, 512, nullptr, nullptr, nullptr);

    // 8. FFN down + residual(a)
    gemm64<2><<<dim3(8, 128), 256>>>(ph1, pW2T, b2, pa, py2, 512, nullptr, nullptr, nullptr);

    // 9. final layernorm -> out
    ln_kernel<<<B_ * L_, 256>>>(py2, lnw, lnb, out);
}

// round 6
// speedup vs baseline: 1.6348x; 1.6348x over previous
#include <cuda_runtime.h>
#include <cuda_bf16.h>
#include <math.h>

#define B_ 4
#define L_ 2048
#define H_ 512
#define N_ 8
#define D_ 64

// ---------------- scratch (static device globals; no allocation) ----------------
__device__ float g_Wqkv[H_ * 3 * H_];   // [h][mat*512 + n*64 + d]
__device__ float g_bqkv[3 * H_];
__device__ float g_Wrp[H_ * H_];        // [h][n*64+d]
__device__ float g_brp[H_];
__device__ float g_WcT[H_ * H_];        // [k][c] = Wc[c][k]
__device__ float g_W1T[H_ * H_];
__device__ float g_W2T[H_ * H_];
__device__ float g_q[B_ * N_ * L_ * D_];
__device__ float g_k[B_ * N_ * L_ * D_];
__device__ float g_v[B_ * N_ * L_ * D_];
__device__ float g_rb[N_ * L_ * D_];
__device__ float g_attn[B_ * L_ * H_];
__device__ float g_y1[B_ * L_ * H_];
__device__ float g_a[B_ * L_ * H_];
__device__ float g_h1[B_ * L_ * H_];
__device__ float g_y2[B_ * L_ * H_];

// ---------------- pack kernel ----------------
__global__ void pack_kernel(const float* __restrict__ Wq, const float* __restrict__ bq,
                            const float* __restrict__ Wk, const float* __restrict__ bk,
                            const float* __restrict__ Wv, const float* __restrict__ bv,
                            const float* __restrict__ Wr, const float* __restrict__ br,
                            const float* __restrict__ Wc, const float* __restrict__ W1,
                            const float* __restrict__ W2) {
    int idx = blockIdx.x * blockDim.x + threadIdx.x;
    int stride = gridDim.x * blockDim.x;
    // Wqkv: B matrix [h=512][c=1536], c = mat*512 + n*64 + d ; W{q,k,v}[n][h][d]
    for (int i = idx; i < 512 * 1536; i += stride) {
        int h = i / 1536, c = i % 1536;
        int mat = c >> 9, rem = c & 511, n = rem >> 6, d = rem & 63;
        const float* W = (mat == 0) ? Wq : ((mat == 1) ? Wk : Wv);
        g_Wqkv[i] = W[(n * 512 + h) * 64 + d];
    }
    for (int i = idx; i < 1536; i += stride) {
        int mat = i >> 9, rem = i & 511;
        const float* bb = (mat == 0) ? bq : ((mat == 1) ? bk : bv);
        g_bqkv[i] = bb[rem];
    }
    for (int i = idx; i < 512 * 512; i += stride) {
        int h = i >> 9, c = i & 511;
        int n = c >> 6, d = c & 63;
        g_Wrp[i] = Wr[(n * 512 + h) * 64 + d];
    }
    for (int i = idx; i < 512; i += stride) g_brp[i] = br[i];
    for (int i = idx; i < 512 * 512; i += stride) {
        int k = i >> 9, c = i & 511;
        g_WcT[i] = Wc[c * 512 + k];
        g_W1T[i] = W1[c * 512 + k];
        g_W2T[i] = W2[c * 512 + k];
    }
}

__device__ __forceinline__ float gelu_f(float v) {
    return 0.5f * v * (1.0f + erff(v * 0.70710678118654752f));
}

// ---------------- generic 64x64-tile SGEMM, K=512 ----------------
// MODE 0: qkv scatter (+bqkv)   MODE 1: r scatter (+brp)
// MODE 2: C = acc + bias + res  MODE 3: C = gelu(acc + bias)
template <int MODE>
__global__ void gemm64(const float* __restrict__ A, const float* __restrict__ Bm,
                       const float* __restrict__ bias, const float* __restrict__ res,
                       float* __restrict__ C, int Nc,
                       float* __restrict__ qd, float* __restrict__ kd, float* __restrict__ vd) {
    const int K = 512;
    __shared__ float As[16][68];
    __shared__ float Bs[16][68];
    int tid = threadIdx.x;
    int tx = tid & 15, ty = tid >> 4;
    int m0 = blockIdx.y * 64, c0 = blockIdx.x * 64;
    float acc[4][4];
#pragma unroll
    for (int r = 0; r < 4; r++)
#pragma unroll
        for (int c = 0; c < 4; c++) acc[r][c] = 0.f;

    int am = tid >> 2, ak = (tid & 3) * 4;
    int bk = tid >> 4, bcol = (tid & 15) * 4;

    for (int k0 = 0; k0 < K; k0 += 16) {
        float4 av = *(const float4*)&A[(m0 + am) * K + k0 + ak];
        As[ak + 0][am] = av.x;
        As[ak + 1][am] = av.y;
        As[ak + 2][am] = av.z;
        As[ak + 3][am] = av.w;
        *(float4*)&Bs[bk][bcol] = *(const float4*)&Bm[(k0 + bk) * Nc + c0 + bcol];
        __syncthreads();
#pragma unroll
        for (int kk = 0; kk < 16; kk++) {
            float4 a4 = *(const float4*)&As[kk][ty * 4];
            float4 b4 = *(const float4*)&Bs[kk][tx * 4];
            float aa[4] = {a4.x, a4.y, a4.z, a4.w};
            float bb[4] = {b4.x, b4.y, b4.z, b4.w};
#pragma unroll
            for (int r = 0; r < 4; r++)
#pragma unroll
                for (int c = 0; c < 4; c++) acc[r][c] += aa[r] * bb[c];
        }
        __syncthreads();
    }

#pragma unroll
    for (int r = 0; r < 4; r++) {
#pragma unroll
        for (int c = 0; c < 4; c++) {
            int m = m0 + ty * 4 + r;
            int cg = c0 + tx * 4 + c;
            float val = acc[r][c] + bias[cg];
            if (MODE == 0) {
                int mat = cg >> 9, rem = cg & 511, n = rem >> 6, d = rem & 63;
                float* dst = (mat == 0) ? qd : ((mat == 1) ? kd : vd);
                int bI = m >> 11, l = m & 2047;
                dst[((bI * 8 + n) * 2048 + l) * 64 + d] = val;
            } else if (MODE == 1) {
                int n = cg >> 6, d = cg & 63;
                C[(n * 2048 + m) * 64 + d] = val;
            } else if (MODE == 2) {
                C[m * Nc + cg] = val + res[m * Nc + cg];
            } else {
                C[m * Nc + cg] = gelu_f(val);
            }
        }
    }
}

// ---------------- fused causal rel-pos flash attention ----------------
// scores[i,j] = (qc[i]·k[j] + qp[i]·r[L-1-i+j]) / 8, causal j<=i, online softmax.
#define ATTN_SMEM_BYTES ((4 * 64 * 68 + 64 * 132 + 64) * 4)

__global__ void attn_kernel(const float* __restrict__ qg, const float* __restrict__ kg,
                            const float* __restrict__ vg, const float* __restrict__ rg,
                            const float* __restrict__ cb, const float* __restrict__ pb,
                            float* __restrict__ outg) {
    extern __shared__ float sm[];
    float* Qcs = sm;                      // [64][68]  row-major (i, d)
    float* Kst = sm + 4352;               // [64][68]  d-major (d, j)
    float* Vs  = sm + 2 * 4352;           // [64][68]  (j, d)
    float* Ss  = sm + 3 * 4352;           // [64][68]  P tile
    float* Rst = sm + 4 * 4352;           // [64][132] d-major (d, pp)
    float* dlt = sm + 4 * 4352 + 8448;    // [64]  pos_bias - content_bias

    const int tid = threadIdx.x;
    const int tx = tid & 15, ty = tid >> 4;
    const int ib = blockIdx.x, bn = blockIdx.y;
    const int n = bn & 7, b = bn >> 3;
    const int I0 = ib * 64;

    const int lrow = tid >> 4;        // 0..15
    const int ld0 = (tid & 15) * 4;   // 0..60

    const float* qbase = qg + (bn * L_ + I0) * D_;
    float4 cbv = *(const float4*)&cb[n * 64 + ld0];
#pragma unroll
    for (int t = 0; t < 4; t++) {
        int rr = lrow + t * 16;
        float4 qv = *(const float4*)&qbase[rr * 64 + ld0];
        float* dst = &Qcs[rr * 68 + ld0];
        dst[0] = qv.x + cbv.x;
        dst[1] = qv.y + cbv.y;
        dst[2] = qv.z + cbv.z;
        dst[3] = qv.w + cbv.w;
    }
    if (tid < 64) dlt[tid] = pb[n * 64 + tid] - cb[n * 64 + tid];

    float mrow[4], lsum[4], o[4][4];
#pragma unroll
    for (int r = 0; r < 4; r++) {
        mrow[r] = -1e30f;
        lsum[r] = 0.f;
#pragma unroll
        for (int c = 0; c < 4; c++) o[r][c] = 0.f;
    }

    const int r0 = ty * 4, c0 = tx * 4;
    const int wbase = 60 - r0 + c0;   // multiple of 4, in [0,120]

    for (int jb = 0; jb <= ib; jb++) {
        __syncthreads();
        const int J0 = jb * 64;
        const int pmin = L_ - 64 - I0 + J0;
        const float* kbase = kg + (bn * L_ + J0) * D_;
        const float* vbase = vg + (bn * L_ + J0) * D_;
#pragma unroll
        for (int t = 0; t < 4; t++) {
            int j = lrow + t * 16;
            float4 kv = *(const float4*)&kbase[j * 64 + ld0];
            Kst[(ld0 + 0) * 68 + j] = kv.x;
            Kst[(ld0 + 1) * 68 + j] = kv.y;
            Kst[(ld0 + 2) * 68 + j] = kv.z;
            Kst[(ld0 + 3) * 68 + j] = kv.w;
            *(float4*)&Vs[j * 68 + ld0] = *(const float4*)&vbase[j * 64 + ld0];
        }
        const float* rbase = rg + n * (L_ * D_);
#pragma unroll
        for (int t = 0; t < 8; t++) {
            int pp = lrow + t * 16;
            int p = pmin + pp;
            float4 rv = make_float4(0.f, 0.f, 0.f, 0.f);
            if (p < L_) rv = *(const float4*)&rbase[p * 64 + ld0];
            Rst[(ld0 + 0) * 132 + pp] = rv.x;
            Rst[(ld0 + 1) * 132 + pp] = rv.y;
            Rst[(ld0 + 2) * 132 + pp] = rv.z;
            Rst[(ld0 + 3) * 132 + pp] = rv.w;
        }
        __syncthreads();

        float s[4][4];
#pragma unroll
        for (int r = 0; r < 4; r++)
#pragma unroll
            for (int c = 0; c < 4; c++) s[r][c] = 0.f;

#pragma unroll 4
        for (int kk = 0; kk < 64; kk++) {
            float d = dlt[kk];
            float aq[4], ap[4];
#pragma unroll
            for (int r = 0; r < 4; r++) {
                aq[r] = Qcs[(r0 + r) * 68 + kk];
                ap[r] = aq[r] + d;
            }
            float4 kb = *(const float4*)&Kst[kk * 68 + c0];
            float kbv[4] = {kb.x, kb.y, kb.z, kb.w};
            float4 w0 = *(const float4*)&Rst[kk * 132 + wbase];
            float4 w1 = *(const float4*)&Rst[kk * 132 + wbase + 4];
            float w[8] = {w0.x, w0.y, w0.z, w0.w, w1.x, w1.y, w1.z, w1.w};
#pragma unroll
            for (int r = 0; r < 4; r++)
#pragma unroll
                for (int c = 0; c < 4; c++)
                    s[r][c] += aq[r] * kbv[c] + ap[r] * w[3 - r + c];
        }

        const bool diag = (jb == ib);
#pragma unroll
        for (int r = 0; r < 4; r++)
#pragma unroll
            for (int c = 0; c < 4; c++) {
                s[r][c] *= 0.125f;
                if (diag && (J0 + c0 + c) > (I0 + r0 + r)) s[r][c] = -1e30f;
            }

#pragma unroll
        for (int r = 0; r < 4; r++) {
            float rm = fmaxf(fmaxf(s[r][0], s[r][1]), fmaxf(s[r][2], s[r][3]));
#pragma unroll
            for (int mk = 8; mk >= 1; mk >>= 1)
                rm = fmaxf(rm, __shfl_xor_sync(0xffffffffu, rm, mk));
            float mn = fmaxf(mrow[r], rm);
            float alpha = __expf(mrow[r] - mn);
            mrow[r] = mn;
            float rs = 0.f;
#pragma unroll
            for (int c = 0; c < 4; c++) {
                s[r][c] = __expf(s[r][c] - mn);
                rs += s[r][c];
            }
#pragma unroll
            for (int mk = 8; mk >= 1; mk >>= 1)
                rs += __shfl_xor_sync(0xffffffffu, rs, mk);
            lsum[r] = lsum[r] * alpha + rs;
#pragma unroll
            for (int c = 0; c < 4; c++) o[r][c] *= alpha;
        }

#pragma unroll
        for (int r = 0; r < 4; r++)
            *(float4*)&Ss[(r0 + r) * 68 + c0] = make_float4(s[r][0], s[r][1], s[r][2], s[r][3]);
        __syncthreads();

#pragma unroll 8
        for (int jj = 0; jj < 64; jj++) {
            float ap2[4];
#pragma unroll
            for (int r = 0; r < 4; r++) ap2[r] = Ss[(r0 + r) * 68 + jj];
            float4 bv = *(const float4*)&Vs[jj * 68 + c0];
            float bvv[4] = {bv.x, bv.y, bv.z, bv.w};
#pragma unroll
            for (int r = 0; r < 4; r++)
#pragma unroll
                for (int c = 0; c < 4; c++) o[r][c] += ap2[r] * bvv[c];
        }
    }

#pragma unroll
    for (int r = 0; r < 4; r++) {
        float inv = 1.0f / lsum[r];
        float* od = &outg[(b * L_ + I0 + r0 + r) * H_ + n * 64 + c0];
        od[0] = o[r][0] * inv;
        od[1] = o[r][1] * inv;
        od[2] = o[r][2] * inv;
        od[3] = o[r][3] * inv;
    }
}

// ---------------- layernorm (eps=1e-12), 1 block per row of 512 ----------------
__global__ void ln_kernel(const float* __restrict__ in, const float* __restrict__ w,
                          const float* __restrict__ bparm, float* __restrict__ out) {
    __shared__ float red[8];
    __shared__ float stat[2];
    int row = blockIdx.x, tid = threadIdx.x;
    const float* xr = in + row * H_;
    float v0 = xr[tid], v1 = xr[tid + 256];
    float s = v0 + v1;
#pragma unroll
    for (int mk = 16; mk >= 1; mk >>= 1) s += __shfl_xor_sync(0xffffffffu, s, mk);
    if ((tid & 31) == 0) red[tid >> 5] = s;
    __syncthreads();
    if (tid == 0) {
        float t = 0;
#pragma unroll
        for (int i = 0; i < 8; i++) t += red[i];
        stat[0] = t * (1.0f / H_);
    }
    __syncthreads();
    float u = stat[0];
    float d0 = v0 - u, d1 = v1 - u;
    float q = d0 * d0 + d1 * d1;
#pragma unroll
    for (int mk = 16; mk >= 1; mk >>= 1) q += __shfl_xor_sync(0xffffffffu, q, mk);
    __syncthreads();
    if ((tid & 31) == 0) red[tid >> 5] = q;
    __syncthreads();
    if (tid == 0) {
        float t = 0;
#pragma unroll
        for (int i = 0; i < 8; i++) t += red[i];
        stat[1] = rsqrtf(t * (1.0f / H_) + 1e-12f);
    }
    __syncthreads();
    float inv = stat[1];
    out[row * H_ + tid] = w[tid] * d0 * inv + bparm[tid];
    out[row * H_ + tid + 256] = w[tid + 256] * d1 * inv + bparm[tid + 256];
}

// ---------------- launch ----------------
extern "C" void kernel_launch(void* const* d_in, const int* in_sizes, int n_in,
                              void* d_out, int out_size) {
    (void)in_sizes; (void)n_in; (void)out_size;
    const float* x  = (const float*)d_in[0];
    const float* pe = (const float*)d_in[1];
    const float* Wq = (const float*)d_in[2];
    const float* bq = (const float*)d_in[3];
    const float* Wk = (const float*)d_in[4];
    const float* bk = (const float*)d_in[5];
    const float* Wv = (const float*)d_in[6];
    const float* bv = (const float*)d_in[7];
    const float* Wr = (const float*)d_in[8];
    const float* br = (const float*)d_in[9];
    const float* cb = (const float*)d_in[10];
    const float* pb = (const float*)d_in[11];
    const float* Wc = (const float*)d_in[12];
    const float* bc = (const float*)d_in[13];
    const float* W1 = (const float*)d_in[14];
    const float* b1 = (const float*)d_in[15];
    const float* W2 = (const float*)d_in[16];
    const float* b2 = (const float*)d_in[17];
    const float* lnw = (const float*)d_in[18];
    const float* lnb = (const float*)d_in[19];
    float* out = (float*)d_out;

    float *pWqkv, *pbqkv, *pWrp, *pbrp, *pWcT, *pW1T, *pW2T;
    float *pq, *pk, *pv, *pr, *pattn, *py1, *pa, *ph1, *py2;
    cudaGetSymbolAddress((void**)&pWqkv, g_Wqkv);
    cudaGetSymbolAddress((void**)&pbqkv, g_bqkv);
    cudaGetSymbolAddress((void**)&pWrp, g_Wrp);
    cudaGetSymbolAddress((void**)&pbrp, g_brp);
    cudaGetSymbolAddress((void**)&pWcT, g_WcT);
    cudaGetSymbolAddress((void**)&pW1T, g_W1T);
    cudaGetSymbolAddress((void**)&pW2T, g_W2T);
    cudaGetSymbolAddress((void**)&pq, g_q);
    cudaGetSymbolAddress((void**)&pk, g_k);
    cudaGetSymbolAddress((void**)&pv, g_v);
    cudaGetSymbolAddress((void**)&pr, g_rb);
    cudaGetSymbolAddress((void**)&pattn, g_attn);
    cudaGetSymbolAddress((void**)&py1, g_y1);
    cudaGetSymbolAddress((void**)&pa, g_a);
    cudaGetSymbolAddress((void**)&ph1, g_h1);
    cudaGetSymbolAddress((void**)&py2, g_y2);

    cudaFuncSetAttribute(attn_kernel, cudaFuncAttributeMaxDynamicSharedMemorySize,
                         ATTN_SMEM_BYTES);

    // 1. pack weights
    pack_kernel<<<768, 256>>>(Wq, bq, Wk, bk, Wv, bv, Wr, br, Wc, W1, W2);

    // 2. QKV projection: (8192x512) @ (512x1536), scatter into per-head layout
    gemm64<0><<<dim3(24, 128), 256>>>(x, pWqkv, pbqkv, nullptr, nullptr, 1536, pq, pk, pv);

    // 3. R projection: (2048x512) @ (512x512)
    gemm64<1><<<dim3(8, 32), 256>>>(pe, pWrp, pbrp, nullptr, pr, 512, nullptr, nullptr, nullptr);

    // 4. fused causal rel-pos attention
    attn_kernel<<<dim3(L_ / 64, B_ * N_), 256, ATTN_SMEM_BYTES>>>(pq, pk, pv, pr, cb, pb, pattn);

    // 5. output projection + residual(x)
    gemm64<2><<<dim3(8, 128), 256>>>(pattn, pWcT, bc, x, py1, 512, nullptr, nullptr, nullptr);

    // 6. layernorm -> a
    ln_kernel<<<B_ * L_, 256>>>(py1, lnw, lnb, pa);

    // 7. FFN up + GELU
    gemm64<3><<<dim3(8, 128), 256>>>(pa, pW1T, b1, nullptr, ph1, 512, nullptr, nullptr, nullptr);

    // 8. FFN down + residual(a)
    gemm64<2><<<dim3(8, 128), 256>>>(ph1, pW2T, b2, pa, py2, 512, nullptr, nullptr, nullptr);

    // 9. final layernorm -> out
    ln_kernel<<<B_ * L_, 256>>>(py2, lnw, lnb, out);
}